// round 9
// baseline (speedup 1.0000x reference)
#include <cuda_runtime.h>
#include <cuda_fp16.h>
#include <cstdint>

#define BATCH 64
#define TIME  2048
#define FEAT  256
#define MROWS (BATCH * TIME)
#define EPS_V 1e-7f

// ---------------- scratch (static device globals; alloc-free rule) ----------
__device__ __half g_Wh[FEAT * FEAT];             // g_Wh[n*FEAT+k] = (half)W[k][n]
__device__ float  g_part[(MROWS / 128) * FEAT];  // per-CTA numerator partials
__device__ float  g_denp[MROWS / 128];           // per-CTA denominator partials

__device__ __forceinline__ uint32_t h2_as_u32(__half2 h) {
    return *reinterpret_cast<uint32_t*>(&h);
}
__device__ __forceinline__ uint32_t smem_u32(const void* p) {
    uint32_t a;
    asm("{ .reg .u64 t; cvta.to.shared.u64 t, %1; cvt.u32.u64 %0, t; }" : "=r"(a) : "l"(p));
    return a;
}

// ---------------- k0: tiled transpose W[k][n] -> g_Wh[n][k] (half) ----------
__global__ __launch_bounds__(256)
void k0_wh(const float* __restrict__ W) {
    __shared__ float t[32][33];
    const int tx = threadIdx.x, ty = threadIdx.y;
    const int x0 = blockIdx.x * 32, y0 = blockIdx.y * 32;
    #pragma unroll
    for (int i = 0; i < 4; i++)
        t[ty + i * 8][tx] = W[(y0 + ty + i * 8) * FEAT + x0 + tx];
    __syncthreads();
    #pragma unroll
    for (int i = 0; i < 4; i++)
        g_Wh[(x0 + ty + i * 8) * FEAT + y0 + tx] = __float2half_rn(t[tx][ty + i * 8]);
}

// ---------------- k1: fp16 mma GEMM + tanh + u-dot + exp + weighted-x -------
#define BM 128
#define BN 256
#define BK 64
#define KT (FEAT / BK)          // 4
#define K1_THREADS 256          // 8 warps: wm = wid%2 (64 M-rows), wn = wid/2 (64 N-cols)

#define STRIDE   144
#define A_BYTES  (BM * STRIDE)            // 18432
#define B_BYTES  (BN * STRIDE)            // 36864
#define STAGE    (A_BYTES + B_BYTES)      // 55296
#define RED_OFF  (2 * STAGE)              // red[4][128] floats
#define ES_OFF   (RED_OFF + 2048)         // e_s[128]
#define WP_OFF   (ES_OFF + 512)           // wp[8]
#define SMEM_SZ  (WP_OFF + 32)

__device__ __forceinline__ void mma_f16(float* d, const uint32_t* a, uint32_t b0, uint32_t b1) {
    asm volatile(
        "mma.sync.aligned.m16n8k16.row.col.f32.f16.f16.f32 "
        "{%0,%1,%2,%3}, {%4,%5,%6,%7}, {%8,%9}, {%0,%1,%2,%3};"
        : "+f"(d[0]), "+f"(d[1]), "+f"(d[2]), "+f"(d[3])
        : "r"(a[0]), "r"(a[1]), "r"(a[2]), "r"(a[3]), "r"(b0), "r"(b1));
}
__device__ __forceinline__ void ldsm4(uint32_t* d, uint32_t addr) {
    asm volatile("ldmatrix.sync.aligned.m8n8.x4.shared.b16 {%0,%1,%2,%3}, [%4];"
                 : "=r"(d[0]), "=r"(d[1]), "=r"(d[2]), "=r"(d[3]) : "r"(addr));
}

// A: 128 rows x 64 halfs per stage, at stageBase + row*STRIDE
__device__ __forceinline__ void loadA(const float* __restrict__ x, char* stageBase,
                                      size_t rowBase, int k0, int tid) {
    #pragma unroll
    for (int i = 0; i < 8; i++) {
        const int f4 = tid + i * K1_THREADS;
        const int row = f4 >> 4, q = f4 & 15;
        const float4 v = *reinterpret_cast<const float4*>(&x[(rowBase + row) * FEAT + k0 + q * 4]);
        const uint32_t h0 = h2_as_u32(__floats2half2_rn(v.x, v.y));
        const uint32_t h1 = h2_as_u32(__floats2half2_rn(v.z, v.w));
        *reinterpret_cast<uint2*>(stageBase + row * STRIDE + q * 8) = make_uint2(h0, h1);
    }
}
// B: 256 rows x 64 halfs per stage, at stageBase + A_BYTES + n*STRIDE
__device__ __forceinline__ void loadB(char* stageBase, int k0, int tid) {
    char* bBase = stageBase + A_BYTES;
    #pragma unroll
    for (int i = 0; i < 8; i++) {
        const int ch = tid + i * K1_THREADS;
        const int n = ch >> 3, q = ch & 7;
        uint32_t d;
        asm("{ .reg .u64 t; cvta.to.shared.u64 t, %1; cvt.u32.u64 %0, t; }"
            : "=r"(d) : "l"(bBase + n * STRIDE + q * 16));
        asm volatile("cp.async.cg.shared.global [%0], [%1], 16;"
                     :: "r"(d), "l"(g_Wh + n * FEAT + k0 + q * 8) : "memory");
    }
    asm volatile("cp.async.commit_group;" ::: "memory");
}

__global__ __launch_bounds__(K1_THREADS, 1)
void k1_mma(const float* __restrict__ x, const float* __restrict__ bias,
            const float* __restrict__ u)
{
    extern __shared__ char smem[];
    const uint32_t sb = smem_u32(smem);
    const int tid = threadIdx.x;
    const int wid = tid >> 5, l = tid & 31;
    const int wm = wid & 1, wn = wid >> 1;       // wm: 0..1 (64 rows), wn: 0..3 (64 cols)
    const int lq = l >> 2, lr = l & 3;
    const size_t rowBase = (size_t)blockIdx.x * BM;

    // ldmatrix per-thread source offsets (within a stage)
    const uint32_t aOff = (uint32_t)((wm * 64 + (l & 7) + ((l >> 3) & 1) * 8) * STRIDE
                                     + ((l >> 4) & 1) * 16);
    const uint32_t bOff = (uint32_t)(A_BYTES + (wn * 64 + (l & 7) + ((l >> 4) & 1) * 8) * STRIDE
                                     + ((l >> 3) & 1) * 16);

    float acc[4][8][4];
    #pragma unroll
    for (int mt = 0; mt < 4; mt++)
        #pragma unroll
        for (int nt = 0; nt < 8; nt++)
            #pragma unroll
            for (int c = 0; c < 4; c++) acc[mt][nt][c] = 0.0f;

    // ---- prologue: stage 0 ----
    loadB(smem, 0, tid);
    loadA(x, smem, rowBase, 0, tid);

    for (int kt = 0; kt < KT; kt++) {
        const uint32_t stU = sb + (kt & 1) * STAGE;
        asm volatile("cp.async.wait_group 0;" ::: "memory");
        __syncthreads();

        if (kt < KT - 1) {
            char* nxt = smem + ((kt + 1) & 1) * STAGE;
            loadB(nxt, (kt + 1) * BK, tid);
            loadA(x, nxt, rowBase, (kt + 1) * BK, tid);
        }

        // ---- compute 4 k16-steps from stage kt ----
        #pragma unroll
        for (int ks = 0; ks < 4; ks++) {
            uint32_t af[4][4];
            #pragma unroll
            for (int mt = 0; mt < 4; mt++)
                ldsm4(af[mt], stU + aOff + mt * 16 * STRIDE + ks * 32);
            #pragma unroll
            for (int p = 0; p < 4; p++) {
                uint32_t bf[4];
                ldsm4(bf, stU + bOff + p * 16 * STRIDE + ks * 32);
                #pragma unroll
                for (int mt = 0; mt < 4; mt++) {
                    mma_f16(acc[mt][2 * p],     af[mt], bf[0], bf[1]);
                    mma_f16(acc[mt][2 * p + 1], af[mt], bf[2], bf[3]);
                }
            }
        }
    }

    // ---- epilogue stage 1: tanh + u-dot, reduce to per-row ait -------------
    float bv[16], uv[16];
    #pragma unroll
    for (int nt = 0; nt < 8; nt++)
        #pragma unroll
        for (int d = 0; d < 2; d++) {
            const int col = wn * 64 + nt * 8 + lr * 2 + d;
            bv[nt * 2 + d] = bias[col];
            uv[nt * 2 + d] = u[col];
        }

    float* red = reinterpret_cast<float*>(smem + RED_OFF);   // [4][128]
    float* e_s = reinterpret_cast<float*>(smem + ES_OFF);
    float* wp  = reinterpret_cast<float*>(smem + WP_OFF);
    __syncthreads();
    #pragma unroll
    for (int mt = 0; mt < 4; mt++) {
        float p0 = 0.0f, p1 = 0.0f;
        #pragma unroll
        for (int nt = 0; nt < 8; nt++)
            #pragma unroll
            for (int d = 0; d < 2; d++) {
                {
                    const float v = acc[mt][nt][d] + bv[nt * 2 + d];
                    const float t = 1.0f - __fdividef(2.0f, __expf(v + v) + 1.0f);
                    p0 = fmaf(t, uv[nt * 2 + d], p0);
                }
                {
                    const float v = acc[mt][nt][2 + d] + bv[nt * 2 + d];
                    const float t = 1.0f - __fdividef(2.0f, __expf(v + v) + 1.0f);
                    p1 = fmaf(t, uv[nt * 2 + d], p1);
                }
            }
        #pragma unroll
        for (int off = 2; off > 0; off >>= 1) {
            p0 += __shfl_xor_sync(0xffffffffu, p0, off);
            p1 += __shfl_xor_sync(0xffffffffu, p1, off);
        }
        if (lr == 0) {
            red[wn * BM + wm * 64 + mt * 16 + lq]     = p0;
            red[wn * BM + wm * 64 + mt * 16 + lq + 8] = p1;
        }
    }
    __syncthreads();

    // ---- epilogue stage 2: e = exp(ait); denominator partial ---------------
    if (tid < BM) {
        const float s = red[tid] + red[BM + tid] + red[2 * BM + tid] + red[3 * BM + tid];
        const float e = expf(s);
        e_s[tid] = e;
        float w = e;
        #pragma unroll
        for (int off = 16; off > 0; off >>= 1)
            w += __shfl_xor_sync(0xffffffffu, w, off);
        if (l == 0) wp[wid] = w;
    }
    __syncthreads();
    if (tid == 0)
        g_denp[blockIdx.x] = wp[0] + wp[1] + wp[2] + wp[3];

    // ---- epilogue stage 3: numerator partial (x tile L2-resident) ----------
    {
        const float* xp = x + rowBase * FEAT + tid;
        float a0 = 0.0f, a1 = 0.0f;
        #pragma unroll 8
        for (int i = 0; i < BM; i += 2) {
            a0 = fmaf(xp[(size_t)i * FEAT], e_s[i], a0);
            a1 = fmaf(xp[(size_t)(i + 1) * FEAT], e_s[i + 1], a1);
        }
        g_part[blockIdx.x * FEAT + tid] = a0 + a1;
    }
}

// ---------------- k_final: out[b,f] = num/(den+eps) -------------------------
#define CTAS_PER_B (TIME / BM)   // 16
__global__ __launch_bounds__(256)
void k_final(float* __restrict__ out) {
    const int b = blockIdx.x, tid = threadIdx.x;
    float den = 0.0f;
    #pragma unroll
    for (int i = 0; i < CTAS_PER_B; i++)
        den += g_denp[b * CTAS_PER_B + i];
    float num = 0.0f;
    #pragma unroll
    for (int i = 0; i < CTAS_PER_B; i++)
        num += g_part[(b * CTAS_PER_B + i) * FEAT + tid];
    out[b * FEAT + tid] = num / (den + EPS_V);
}

// ---------------------------------------------------------------------------
extern "C" void kernel_launch(void* const* d_in, const int* in_sizes, int n_in,
                              void* d_out, int out_size) {
    const float* x = (const float*)d_in[0];
    const float* W = (const float*)d_in[1];
    const float* b = (const float*)d_in[2];
    const float* u = (const float*)d_in[3];
    float* out = (float*)d_out;

    cudaFuncSetAttribute(k1_mma, cudaFuncAttributeMaxDynamicSharedMemorySize, SMEM_SZ);

    dim3 tb(32, 8);
    dim3 tg(FEAT / 32, FEAT / 32);
    k0_wh<<<tg, tb>>>(W);
    k1_mma<<<MROWS / BM, K1_THREADS, SMEM_SZ>>>(x, b, u);
    k_final<<<BATCH, FEAT>>>(out);
}

// round 10
// speedup vs baseline: 1.2021x; 1.2021x over previous
#include <cuda_runtime.h>
#include <cuda_fp16.h>
#include <cstdint>

#define BATCH 64
#define TIME  2048
#define FEAT  256
#define MROWS (BATCH * TIME)
#define EPS_V 1e-7f

// ---------------- scratch (static device globals; alloc-free rule) ----------
__device__ __half g_Wh[FEAT * FEAT];             // g_Wh[n*FEAT+k] = (half)W[k][n]
__device__ float  g_part[(MROWS / 128) * FEAT];  // per-CTA numerator partials
__device__ float  g_denp[MROWS / 128];           // per-CTA denominator partials

__device__ __forceinline__ uint32_t h2_as_u32(__half2 h) {
    return *reinterpret_cast<uint32_t*>(&h);
}
__device__ __forceinline__ uint32_t smem_u32(const void* p) {
    uint32_t a;
    asm("{ .reg .u64 t; cvta.to.shared.u64 t, %1; cvt.u32.u64 %0, t; }" : "=r"(a) : "l"(p));
    return a;
}

// ---------------- k0: tiled transpose W[k][n] -> g_Wh[n][k] (half) ----------
__global__ __launch_bounds__(256)
void k0_wh(const float* __restrict__ W) {
    __shared__ float t[32][33];
    const int tx = threadIdx.x, ty = threadIdx.y;
    const int x0 = blockIdx.x * 32, y0 = blockIdx.y * 32;
    #pragma unroll
    for (int i = 0; i < 4; i++)
        t[ty + i * 8][tx] = W[(y0 + ty + i * 8) * FEAT + x0 + tx];
    __syncthreads();
    #pragma unroll
    for (int i = 0; i < 4; i++)
        g_Wh[(x0 + ty + i * 8) * FEAT + y0 + tx] = __float2half_rn(t[tx][ty + i * 8]);
}

// ---------------- k1: fp16 mma GEMM + tanh + u-dot + exp + weighted-x -------
#define BM 128
#define BN 256
#define BK 64
#define KT (FEAT / BK)          // 4
#define K1_THREADS 512          // 16 warps: wm = wid%4 (32 M-rows), wn = wid/4 (64 N-cols)

#define STRIDE   144            // bytes per smem row; LDSM 8-row phases conflict-free
#define A_BYTES  (BM * STRIDE)            // 18432
#define B_BYTES  (BN * STRIDE)            // 36864
#define STAGE    (A_BYTES + B_BYTES)      // 55296
#define RED_OFF  (2 * STAGE)              // red[4][128] floats (2048B)
#define ES_OFF   (RED_OFF + 2048)         // e_s[128]
#define WP_OFF   (ES_OFF + 512)           // wp[4]
#define SMEM_SZ  (WP_OFF + 32)

__device__ __forceinline__ void mma_f16(float* d, const uint32_t* a, uint32_t b0, uint32_t b1) {
    asm volatile(
        "mma.sync.aligned.m16n8k16.row.col.f32.f16.f16.f32 "
        "{%0,%1,%2,%3}, {%4,%5,%6,%7}, {%8,%9}, {%0,%1,%2,%3};"
        : "+f"(d[0]), "+f"(d[1]), "+f"(d[2]), "+f"(d[3])
        : "r"(a[0]), "r"(a[1]), "r"(a[2]), "r"(a[3]), "r"(b0), "r"(b1));
}
__device__ __forceinline__ void ldsm4(uint32_t* d, uint32_t addr) {
    asm volatile("ldmatrix.sync.aligned.m8n8.x4.shared.b16 {%0,%1,%2,%3}, [%4];"
                 : "=r"(d[0]), "=r"(d[1]), "=r"(d[2]), "=r"(d[3]) : "r"(addr));
}

__global__ __launch_bounds__(K1_THREADS, 1)
void k1_mma(const float* __restrict__ x, const float* __restrict__ bias,
            const float* __restrict__ u)
{
    extern __shared__ char smem[];
    const uint32_t sb = smem_u32(smem);
    const int tid = threadIdx.x;
    const int wid = tid >> 5, l = tid & 31;
    const int wm = wid & 3, wn = wid >> 2;      // wm: 32 M-rows; wn: 64 N-cols
    const int lq = l >> 2, lr = l & 3;
    const size_t rowBase = (size_t)blockIdx.x * BM;

    // ldmatrix per-thread source offsets (stage-relative)
    const uint32_t aOff = (uint32_t)((wm * 32 + (l & 7) + ((l >> 3) & 1) * 8) * STRIDE
                                     + ((l >> 4) & 1) * 16);
    const uint32_t bOff = (uint32_t)(A_BYTES + (wn * 64 + (l & 7) + ((l >> 4) & 1) * 8) * STRIDE
                                     + ((l >> 3) & 1) * 16);

    float acc[2][8][4];
    #pragma unroll
    for (int mt = 0; mt < 2; mt++)
        #pragma unroll
        for (int nt = 0; nt < 8; nt++)
            #pragma unroll
            for (int c = 0; c < 4; c++) acc[mt][nt][c] = 0.0f;

    // ---- prologue ----
    float4 areg[4];
    {
        #pragma unroll
        for (int i = 0; i < 4; i++) {
            const int f4 = tid + i * K1_THREADS;
            const int row = f4 >> 4, q = f4 & 15;
            areg[i] = *reinterpret_cast<const float4*>(&x[(rowBase + row) * FEAT + q * 4]);
        }
        #pragma unroll
        for (int i = 0; i < 4; i++) {
            const int ch = tid + i * K1_THREADS;
            const int n = ch >> 3, q = ch & 7;
            uint32_t dst;
            asm("{ .reg .u64 t; cvta.to.shared.u64 t, %1; cvt.u32.u64 %0, t; }"
                : "=r"(dst) : "l"(smem + A_BYTES + n * STRIDE + q * 16));
            asm volatile("cp.async.cg.shared.global [%0], [%1], 16;"
                         :: "r"(dst), "l"(g_Wh + n * FEAT + q * 8) : "memory");
        }
        asm volatile("cp.async.commit_group;" ::: "memory");
    }

    for (int kt = 0; kt < KT; kt++) {
        char* Ab = smem + (kt & 1) * STAGE;
        const uint32_t stU = sb + (kt & 1) * STAGE;

        // STS A(kt) from regs (cvt fp32 -> half2)
        #pragma unroll
        for (int i = 0; i < 4; i++) {
            const int f4 = tid + i * K1_THREADS;
            const int row = f4 >> 4, q = f4 & 15;
            uint32_t h0 = h2_as_u32(__floats2half2_rn(areg[i].x, areg[i].y));
            uint32_t h1 = h2_as_u32(__floats2half2_rn(areg[i].z, areg[i].w));
            *reinterpret_cast<uint2*>(Ab + row * STRIDE + q * 8) = make_uint2(h0, h1);
        }
        asm volatile("cp.async.wait_group 0;" ::: "memory");
        __syncthreads();

        if (kt < KT - 1) {
            const int k0 = (kt + 1) * BK;
            char* Bn = smem + ((kt + 1) & 1) * STAGE + A_BYTES;
            #pragma unroll
            for (int i = 0; i < 4; i++) {
                const int ch = tid + i * K1_THREADS;
                const int n = ch >> 3, q = ch & 7;
                uint32_t dst;
                asm("{ .reg .u64 t; cvta.to.shared.u64 t, %1; cvt.u32.u64 %0, t; }"
                    : "=r"(dst) : "l"(Bn + n * STRIDE + q * 16));
                asm volatile("cp.async.cg.shared.global [%0], [%1], 16;"
                             :: "r"(dst), "l"(g_Wh + n * FEAT + k0 + q * 8) : "memory");
            }
            asm volatile("cp.async.commit_group;" ::: "memory");
            #pragma unroll
            for (int i = 0; i < 4; i++) {
                const int f4 = tid + i * K1_THREADS;
                const int row = f4 >> 4, q = f4 & 15;
                areg[i] = *reinterpret_cast<const float4*>(&x[(rowBase + row) * FEAT + k0 + q * 4]);
            }
        }

        // ---- compute: 4 k16-steps via ldmatrix ----
        #pragma unroll
        for (int ks = 0; ks < 4; ks++) {
            uint32_t af[2][4];
            #pragma unroll
            for (int mt = 0; mt < 2; mt++)
                ldsm4(af[mt], stU + aOff + mt * 16 * STRIDE + ks * 32);
            #pragma unroll
            for (int p = 0; p < 4; p++) {
                uint32_t bf[4];
                ldsm4(bf, stU + bOff + p * 16 * STRIDE + ks * 32);
                #pragma unroll
                for (int mt = 0; mt < 2; mt++) {
                    mma_f16(acc[mt][2 * p],     af[mt], bf[0], bf[1]);
                    mma_f16(acc[mt][2 * p + 1], af[mt], bf[2], bf[3]);
                }
            }
        }
        __syncthreads();
    }

    // ---- epilogue stage 1: tanh + u-dot, reduce to per-row ait -------------
    float bv[16], uv[16];
    #pragma unroll
    for (int nt = 0; nt < 8; nt++)
        #pragma unroll
        for (int d = 0; d < 2; d++) {
            const int col = wn * 64 + nt * 8 + lr * 2 + d;
            bv[nt * 2 + d] = bias[col];
            uv[nt * 2 + d] = u[col];
        }

    float* red = reinterpret_cast<float*>(smem + RED_OFF);   // 512 floats
    float* e_s = reinterpret_cast<float*>(smem + ES_OFF);
    float* wp  = reinterpret_cast<float*>(smem + WP_OFF);
    #pragma unroll
    for (int mt = 0; mt < 2; mt++) {
        float p0 = 0.0f, p1 = 0.0f;
        #pragma unroll
        for (int nt = 0; nt < 8; nt++)
            #pragma unroll
            for (int d = 0; d < 2; d++) {
                {
                    const float v = acc[mt][nt][d] + bv[nt * 2 + d];
                    const float t = 1.0f - __fdividef(2.0f, __expf(v + v) + 1.0f);
                    p0 = fmaf(t, uv[nt * 2 + d], p0);
                }
                {
                    const float v = acc[mt][nt][2 + d] + bv[nt * 2 + d];
                    const float t = 1.0f - __fdividef(2.0f, __expf(v + v) + 1.0f);
                    p1 = fmaf(t, uv[nt * 2 + d], p1);
                }
            }
        #pragma unroll
        for (int off = 2; off > 0; off >>= 1) {
            p0 += __shfl_xor_sync(0xffffffffu, p0, off);
            p1 += __shfl_xor_sync(0xffffffffu, p1, off);
        }
        if (lr == 0) {
            red[wn * BM + wm * 32 + mt * 16 + lq]     = p0;
            red[wn * BM + wm * 32 + mt * 16 + lq + 8] = p1;
        }
    }
    __syncthreads();

    // ---- epilogue stage 2: e = exp(ait); denominator partial ---------------
    if (tid < BM) {
        const float s = red[tid] + red[BM + tid] + red[2 * BM + tid] + red[3 * BM + tid];
        const float e = expf(s);
        e_s[tid] = e;
        float w = e;
        #pragma unroll
        for (int off = 16; off > 0; off >>= 1)
            w += __shfl_xor_sync(0xffffffffu, w, off);
        if (l == 0) wp[wid] = w;
    }
    __syncthreads();
    if (tid == 0)
        g_denp[blockIdx.x] = wp[0] + wp[1] + wp[2] + wp[3];

    // ---- epilogue stage 3: numerator partial (x tile L2-resident) ----------
    {
        const int col = tid & 255;
        const int rowgrp = tid >> 8;              // 0 or 1 -> rows 0..63 / 64..127
        const float* xp = x + (rowBase + (size_t)rowgrp * 64) * FEAT + col;
        const float* ep = e_s + rowgrp * 64;
        float a0 = 0.0f, a1 = 0.0f;
        #pragma unroll 8
        for (int i = 0; i < 64; i += 2) {
            a0 = fmaf(xp[(size_t)i * FEAT], ep[i], a0);
            a1 = fmaf(xp[(size_t)(i + 1) * FEAT], ep[i + 1], a1);
        }
        red[tid] = a0 + a1;     // red reused (after sync above)
    }
    __syncthreads();
    if (tid < FEAT)
        g_part[blockIdx.x * FEAT + tid] = red[tid] + red[FEAT + tid];
}

// ---------------- k_final: out[b,f] = num/(den+eps) -------------------------
#define CTAS_PER_B (TIME / BM)   // 16
__global__ __launch_bounds__(256)
void k_final(float* __restrict__ out) {
    const int b = blockIdx.x, tid = threadIdx.x;
    float den = 0.0f;
    #pragma unroll
    for (int i = 0; i < CTAS_PER_B; i++)
        den += g_denp[b * CTAS_PER_B + i];
    float num = 0.0f;
    #pragma unroll
    for (int i = 0; i < CTAS_PER_B; i++)
        num += g_part[(b * CTAS_PER_B + i) * FEAT + tid];
    out[b * FEAT + tid] = num / (den + EPS_V);
}

// ---------------------------------------------------------------------------
extern "C" void kernel_launch(void* const* d_in, const int* in_sizes, int n_in,
                              void* d_out, int out_size) {
    const float* x = (const float*)d_in[0];
    const float* W = (const float*)d_in[1];
    const float* b = (const float*)d_in[2];
    const float* u = (const float*)d_in[3];
    float* out = (float*)d_out;

    cudaFuncSetAttribute(k1_mma, cudaFuncAttributeMaxDynamicSharedMemorySize, SMEM_SZ);

    dim3 tb(32, 8);
    dim3 tg(FEAT / 32, FEAT / 32);
    k0_wh<<<tg, tb>>>(W);
    k1_mma<<<MROWS / BM, K1_THREADS, SMEM_SZ>>>(x, b, u);
    k_final<<<BATCH, FEAT>>>(out);
}